// round 16
// baseline (speedup 1.0000x reference)
#include <cuda_runtime.h>
#include <cuda_fp16.h>
#include <cstdint>

#define THREADS 384
#define NWARPS  12

// smem layout (bytes)
#define W1F_OFF 0          // [9 kb][16 nb][32 lane] uint2 (b0h,b1h) fp16x2
#define W2F_OFF 36864      // [8][16][32] uint2
#define B1_OFF  69632
#define B2_OFF  70144
#define A_OFF   70656      // NWARPS warp tiles of 32 rows x 152 fp16 (304B pitch)
#define A_PITCH_B 304
#define WARP_TILE_B (32 * A_PITCH_B)                  // 9728
#define SMEM_BYTES (A_OFF + NWARPS * WARP_TILE_B)     // 187392

__device__ int g_seg_arr[2000256];

__device__ __forceinline__ uint32_t packh(float a0, float a1) {
    uint32_t r;
    asm("cvt.rn.f16x2.f32 %0, %1, %2;" : "=r"(r) : "f"(a1), "f"(a0));
    return r;
}
__device__ __forceinline__ void mma_f16(float* c, const uint32_t* a, uint32_t b0, uint32_t b1) {
    asm volatile("mma.sync.aligned.m16n8k16.row.col.f32.f16.f16.f32 "
                 "{%0,%1,%2,%3}, {%4,%5,%6,%7}, {%8,%9}, {%0,%1,%2,%3};"
                 : "+f"(c[0]), "+f"(c[1]), "+f"(c[2]), "+f"(c[3])
                 : "r"(a[0]), "r"(a[1]), "r"(a[2]), "r"(a[3]), "r"(b0), "r"(b1));
}
__device__ __forceinline__ void ldmx4(uint32_t* a, uint32_t saddr) {
    asm volatile("ldmatrix.sync.aligned.m8n8.x4.shared.b16 {%0,%1,%2,%3}, [%4];"
                 : "=r"(a[0]), "=r"(a[1]), "=r"(a[2]), "=r"(a[3]) : "r"(saddr));
}
__device__ __forceinline__ void sts64(uint32_t sa, uint32_t p0, uint32_t p1) {
    asm volatile("st.shared.v2.u32 [%0], {%1, %2};" :: "r"(sa), "r"(p0), "r"(p1));
}
__device__ __forceinline__ void red_v2(float* p, float a, float b) {
    asm volatile("red.global.add.v2.f32 [%0], {%1, %2};"
                 :: "l"(p), "f"(a), "f"(b) : "memory");
}

// ---------------- prep: zero output + seg ids (walker version) ----------------
__global__ void prep_kernel(const void* __restrict__ ptr_raw, float4* __restrict__ out4,
                            int out4_elems, int Bseg, int N) {
    int idx = blockIdx.x * blockDim.x + threadIdx.x;
    if (idx < out4_elems) out4[idx] = make_float4(0.f, 0.f, 0.f, 0.f);

    // walker: one thread per 32 rows — binary search once, then walk forward
    int nWalk = (N + 31) >> 5;
    if (idx < nWalk) {
        const int* p32 = (const int*)ptr_raw;
        const long long* p64 = (const long long*)ptr_raw;
        bool is64 = (p32[Bseg] != N);
        int row0 = idx << 5;
        int rowEnd = row0 + 32; if (rowEnd > N) rowEnd = N;
        int lo = 0, hi = Bseg + 1;
        while (lo < hi) {
            int mid = (lo + hi) >> 1;
            long long v = is64 ? p64[mid] : (long long)p32[mid];
            if (v <= (long long)row0) lo = mid + 1; else hi = mid;
        }
        int s = lo - 1;
        long long nxt = is64 ? p64[s + 1] : (long long)p32[s + 1];
        for (int r = row0; r < rowEnd; ++r) {
            while (nxt <= (long long)r) {
                ++s;
                nxt = is64 ? p64[s + 1] : (long long)p32[s + 1];
            }
            g_seg_arr[r] = s;
        }
    }
}

// ---------------- fused MLP + segment-sum ----------------
__global__ __launch_bounds__(THREADS, 1)
void fused_mma(const float* __restrict__ x, const float* __restrict__ hn,
               const float* __restrict__ W1g, const float* __restrict__ b1g,
               const float* __restrict__ W2g, const float* __restrict__ b2g,
               float* __restrict__ out, int N) {
    extern __shared__ char smc[];
    uint2* W1F = (uint2*)(smc + W1F_OFF);
    uint2* W2F = (uint2*)(smc + W2F_OFF);
    float* b1s = (float*)(smc + B1_OFF);
    float* b2s = (float*)(smc + B2_OFF);

    const int tid  = threadIdx.x;
    const int lane = tid & 31;
    const int wid  = tid >> 5;

    // ---- build fp16 B-fragment images in smem (once per CTA) ----
    for (int s = tid; s < 9 * 16 * 32; s += THREADS) {
        int kb = s >> 9, nb = (s >> 5) & 15, ln = s & 31;
        int k0 = kb * 16 + 2 * (ln & 3);
        int n  = nb * 8 + (ln >> 2);
        uint32_t b0 = packh(W1g[k0 * 128 + n],       W1g[(k0 + 1) * 128 + n]);
        uint32_t b1 = packh(W1g[(k0 + 8) * 128 + n], W1g[(k0 + 9) * 128 + n]);
        W1F[s] = make_uint2(b0, b1);
    }
    for (int s = tid; s < 8 * 16 * 32; s += THREADS) {
        int kb = s >> 9, nb = (s >> 5) & 15, ln = s & 31;
        int k0 = kb * 16 + 2 * (ln & 3);
        int n  = nb * 8 + (ln >> 2);
        uint32_t b0 = packh(W2g[k0 * 128 + n],       W2g[(k0 + 1) * 128 + n]);
        uint32_t b1 = packh(W2g[(k0 + 8) * 128 + n], W2g[(k0 + 9) * 128 + n]);
        W2F[s] = make_uint2(b0, b1);
    }
    if (tid < 128) { b1s[tid] = b1g[tid]; b2s[tid] = b2g[tid]; }
    __syncthreads();

    uint32_t smem_u32;
    asm("{ .reg .u64 t; cvta.to.shared.u64 t, %1; cvt.u32.u64 %0, t; }"
        : "=r"(smem_u32) : "l"(smc));
    const uint32_t tile = smem_u32 + A_OFF + wid * WARP_TILE_B;

    const int rq = lane >> 2;
    const int c0 = 2 * (lane & 3);
    const int totalWarps = gridDim.x * NWARPS;
    const int wgid = blockIdx.x * NWARPS + wid;
    const int nIters = (N + 31) >> 5;
    const unsigned FM = 0xffffffffu;

    // contiguous per-warp iteration range: balanced (+/-1) and sequential
    const int itStart = (int)(((long long)wgid * nIters) / totalWarps);
    const int itEnd   = (int)(((long long)(wgid + 1) * nIters) / totalWarps);

    const int lm_row = lane & 15;
    const int lm_col = (lane >> 4) * 8;

    auto stage = [&](int it) {
        if (it >= nIters) return;
        const int base = it << 5;
        const float4 z4 = make_float4(0.f, 0.f, 0.f, 0.f);
        #pragma unroll
        for (int i = 0; i < 4; ++i) {
            int r = i * 8 + (lane >> 2);
            int g = base + r;
            float4 v = (g < N) ? *(const float4*)(x + (size_t)g * 16 + (lane & 3) * 4) : z4;
            sts64(tile + r * A_PITCH_B + (lane & 3) * 8,
                  packh(v.x, v.y), packh(v.z, v.w));
        }
        #pragma unroll 8
        for (int r = 0; r < 32; ++r) {
            int g = base + r;
            float4 v = (g < N) ? *(const float4*)(hn + (size_t)g * 128 + lane * 4) : z4;
            sts64(tile + r * A_PITCH_B + 32 + lane * 8,
                  packh(v.x, v.y), packh(v.z, v.w));
        }
    };

    stage(itStart);

    for (int it = itStart; it < itEnd; ++it) {
        const int base = it << 5;
        __syncwarp();

        uint32_t hh[2][8][4];   // H fragments (fp16x2)

        // ---- GEMM1: K=144, two N-half passes ----
        #pragma unroll
        for (int hf = 0; hf < 2; ++hf) {
            float acc1[2][8][4];
            #pragma unroll
            for (int c = 0; c < 2; ++c)
                #pragma unroll
                for (int nb = 0; nb < 8; ++nb)
                    #pragma unroll
                    for (int j = 0; j < 4; ++j) acc1[c][nb][j] = 0.f;

            #pragma unroll
            for (int kb = 0; kb < 9; ++kb) {
                uint32_t a[2][4];
                #pragma unroll
                for (int c = 0; c < 2; ++c)
                    ldmx4(a[c], tile + (c * 16 + lm_row) * A_PITCH_B + (kb * 16 + lm_col) * 2);
                const uint2* w = W1F + kb * 512 + hf * 256 + lane;
                #pragma unroll
                for (int nbl = 0; nbl < 8; ++nbl) {
                    uint2 b = w[nbl * 32];
                    mma_f16(acc1[0][nbl], a[0], b.x, b.y);
                    mma_f16(acc1[1][nbl], a[1], b.x, b.y);
                }
            }

            // epilogue1 (this half): bias + relu + fp16 pack -> H fragments
            #pragma unroll
            for (int c = 0; c < 2; ++c) {
                #pragma unroll
                for (int k2 = 0; k2 < 4; ++k2) {
                    int nb0 = 2 * k2, nb1 = nb0 + 1;
                    int g0 = hf * 8 + nb0, g1 = hf * 8 + nb1;
                    float bb00 = b1s[g0 * 8 + c0], bb01 = b1s[g0 * 8 + c0 + 1];
                    float bb10 = b1s[g1 * 8 + c0], bb11 = b1s[g1 * 8 + c0 + 1];
                    uint32_t* hd = hh[c][hf * 4 + k2];
                    hd[0] = packh(fmaxf(acc1[c][nb0][0] + bb00, 0.f),
                                  fmaxf(acc1[c][nb0][1] + bb01, 0.f));
                    hd[1] = packh(fmaxf(acc1[c][nb0][2] + bb00, 0.f),
                                  fmaxf(acc1[c][nb0][3] + bb01, 0.f));
                    hd[2] = packh(fmaxf(acc1[c][nb1][0] + bb10, 0.f),
                                  fmaxf(acc1[c][nb1][1] + bb11, 0.f));
                    hd[3] = packh(fmaxf(acc1[c][nb1][2] + bb10, 0.f),
                                  fmaxf(acc1[c][nb1][3] + bb11, 0.f));
                }
            }
        }

        // A tile consumed; stage next (sequential) iteration under GEMM2
        __syncwarp();
        stage(it + 1);

        // ---- seg ids + reduction masks ----
        int sg[2][2]; bool mk[2][2][3]; bool ld[2][2];
        #pragma unroll
        for (int c = 0; c < 2; ++c) {
            #pragma unroll
            for (int g = 0; g < 2; ++g) {
                int r = base + (2 * c + g) * 8 + rq;
                int s = (r < N) ? g_seg_arr[r] : -1;
                sg[c][g] = s;
                #pragma unroll
                for (int d = 0; d < 3; ++d) {
                    int t = __shfl_down_sync(FM, s, 4 << d);
                    mk[c][g][d] = (rq + (1 << d) < 8) && (t == s);
                }
                int pu = __shfl_up_sync(FM, s, 4);
                ld[c][g] = (rq == 0) || (pu != s);
            }
        }
        // uniform-32 fast-path test (warp-uniform)
        const int segFirst = __shfl_sync(FM, sg[0][0], 0);
        const int segLast  = __shfl_sync(FM, sg[1][1], 28);
        const bool uni32 = (base + 31 < N) && (segFirst == segLast);

        // ---- GEMM2 (K=128) in two N-half passes + fused epilogue2 ----
        #pragma unroll
        for (int nh = 0; nh < 2; ++nh) {
            float acc2[2][8][4];
            #pragma unroll
            for (int c = 0; c < 2; ++c)
                #pragma unroll
                for (int nb = 0; nb < 8; ++nb)
                    #pragma unroll
                    for (int j = 0; j < 4; ++j) acc2[c][nb][j] = 0.f;

            #pragma unroll
            for (int kb2 = 0; kb2 < 8; ++kb2) {
                const uint2* w = W2F + kb2 * 512 + nh * 256 + lane;
                #pragma unroll
                for (int nbl = 0; nbl < 8; ++nbl) {
                    uint2 b = w[nbl * 32];
                    mma_f16(acc2[0][nbl], hh[0][kb2], b.x, b.y);
                    mma_f16(acc2[1][nbl], hh[1][kb2], b.x, b.y);
                }
            }

            if (uni32) {
                // whole 32-row chunk is one segment: collapse groups first
                #pragma unroll
                for (int nbl = 0; nbl < 8; ++nbl) {
                    int nb = nh * 8 + nbl;
                    float bb0 = b2s[nb * 8 + c0], bb1 = b2s[nb * 8 + c0 + 1];
                    float V0 = acc2[0][nbl][0] + acc2[0][nbl][2]
                             + acc2[1][nbl][0] + acc2[1][nbl][2] + 4.f * bb0;
                    float V1 = acc2[0][nbl][1] + acc2[0][nbl][3]
                             + acc2[1][nbl][1] + acc2[1][nbl][3] + 4.f * bb1;
                    #pragma unroll
                    for (int d = 0; d < 3; ++d) {
                        int dd = 4 << d;
                        float t0 = __shfl_down_sync(FM, V0, dd);
                        float t1 = __shfl_down_sync(FM, V1, dd);
                        V0 += t0; V1 += t1;
                    }
                    if (lane < 4)
                        red_v2(out + (size_t)segFirst * 128 + nb * 8 + c0, V0, V1);
                }
            } else {
                #pragma unroll
                for (int c = 0; c < 2; ++c) {
                    #pragma unroll
                    for (int nbl = 0; nbl < 8; ++nbl) {
                        int nb = nh * 8 + nbl;
                        float bb0 = b2s[nb * 8 + c0], bb1 = b2s[nb * 8 + c0 + 1];
                        float v0 = acc2[c][nbl][0] + bb0;
                        float v1 = acc2[c][nbl][1] + bb1;
                        float v2 = acc2[c][nbl][2] + bb0;
                        float v3 = acc2[c][nbl][3] + bb1;
                        #pragma unroll
                        for (int d = 0; d < 3; ++d) {
                            int dd = 4 << d;
                            float t;
                            t = __shfl_down_sync(FM, v0, dd); if (mk[c][0][d]) v0 += t;
                            t = __shfl_down_sync(FM, v1, dd); if (mk[c][0][d]) v1 += t;
                            t = __shfl_down_sync(FM, v2, dd); if (mk[c][1][d]) v2 += t;
                            t = __shfl_down_sync(FM, v3, dd); if (mk[c][1][d]) v3 += t;
                        }
                        if (ld[c][0] && sg[c][0] >= 0)
                            red_v2(out + (size_t)sg[c][0] * 128 + nb * 8 + c0, v0, v1);
                        if (ld[c][1] && sg[c][1] >= 0)
                            red_v2(out + (size_t)sg[c][1] * 128 + nb * 8 + c0, v2, v3);
                    }
                }
            }
        }
    }
}

// ---------------- launch ----------------
extern "C" void kernel_launch(void* const* d_in, const int* in_sizes, int n_in,
                              void* d_out, int out_size) {
    const float* x  = (const float*)d_in[0];
    const float* hn = (const float*)d_in[1];
    const void*  pt = d_in[2];
    const float* W1 = (const float*)d_in[3];
    const float* b1 = (const float*)d_in[4];
    const float* W2 = (const float*)d_in[5];
    const float* b2 = (const float*)d_in[6];
    float* out = (float*)d_out;

    int N    = in_sizes[0] / 16;
    int Bseg = in_sizes[2] - 1;

    int out4 = out_size / 4;
    int nWalk = (N + 31) >> 5;
    int prep_n = (out4 > nWalk) ? out4 : nWalk;
    prep_kernel<<<(prep_n + 255) / 256, 256>>>(pt, (float4*)out, out4, Bseg, N);

    cudaFuncSetAttribute(fused_mma, cudaFuncAttributeMaxDynamicSharedMemorySize, SMEM_BYTES);
    int sms = 0;
    cudaDeviceGetAttribute(&sms, cudaDevAttrMultiProcessorCount, 0);
    if (sms <= 0) sms = 148;
    int nIters = (N + 31) >> 5;
    int maxCtas = (nIters + NWARPS - 1) / NWARPS;
    int grid = (sms < maxCtas) ? sms : maxCtas;
    fused_mma<<<grid, THREADS, SMEM_BYTES>>>(x, hn, W1, b1, W2, b2, out, N);
}

// round 17
// speedup vs baseline: 1.0226x; 1.0226x over previous
#include <cuda_runtime.h>
#include <cuda_fp16.h>
#include <cstdint>

#define THREADS 384
#define NWARPS  12

// smem layout (bytes)
#define W1F_OFF 0          // [9 kb][16 nb][32 lane] uint2 (b0h,b1h) fp16x2
#define W2F_OFF 36864      // [8][16][32] uint2
#define B1_OFF  69632
#define B2_OFF  70144
#define A_OFF   70656      // NWARPS warp tiles of 32 rows x 152 fp16 (304B pitch)
#define A_PITCH_B 304
#define WARP_TILE_B (32 * A_PITCH_B)                  // 9728
#define SMEM_BYTES (A_OFF + NWARPS * WARP_TILE_B)     // 187392

__device__ int g_seg_arr[2000256];

__device__ __forceinline__ uint32_t packh(float a0, float a1) {
    uint32_t r;
    asm("cvt.rn.f16x2.f32 %0, %1, %2;" : "=r"(r) : "f"(a1), "f"(a0));
    return r;
}
__device__ __forceinline__ void mma_f16(float* c, const uint32_t* a, uint32_t b0, uint32_t b1) {
    asm volatile("mma.sync.aligned.m16n8k16.row.col.f32.f16.f16.f32 "
                 "{%0,%1,%2,%3}, {%4,%5,%6,%7}, {%8,%9}, {%0,%1,%2,%3};"
                 : "+f"(c[0]), "+f"(c[1]), "+f"(c[2]), "+f"(c[3])
                 : "r"(a[0]), "r"(a[1]), "r"(a[2]), "r"(a[3]), "r"(b0), "r"(b1));
}
__device__ __forceinline__ void ldmx4(uint32_t* a, uint32_t saddr) {
    asm volatile("ldmatrix.sync.aligned.m8n8.x4.shared.b16 {%0,%1,%2,%3}, [%4];"
                 : "=r"(a[0]), "=r"(a[1]), "=r"(a[2]), "=r"(a[3]) : "r"(saddr));
}
__device__ __forceinline__ void sts64(uint32_t sa, uint32_t p0, uint32_t p1) {
    asm volatile("st.shared.v2.u32 [%0], {%1, %2};" :: "r"(sa), "r"(p0), "r"(p1));
}
__device__ __forceinline__ void red_v2(float* p, float a, float b) {
    asm volatile("red.global.add.v2.f32 [%0], {%1, %2};"
                 :: "l"(p), "f"(a), "f"(b) : "memory");
}

// ---------------- prep: zero output + seg ids (walker version) ----------------
__global__ void prep_kernel(const void* __restrict__ ptr_raw, float4* __restrict__ out4,
                            int out4_elems, int Bseg, int N) {
    int idx = blockIdx.x * blockDim.x + threadIdx.x;
    if (idx < out4_elems) out4[idx] = make_float4(0.f, 0.f, 0.f, 0.f);

    // walker: one thread per 32 rows — binary search once, then walk forward
    int nWalk = (N + 31) >> 5;
    if (idx < nWalk) {
        const int* p32 = (const int*)ptr_raw;
        const long long* p64 = (const long long*)ptr_raw;
        bool is64 = (p32[Bseg] != N);
        int row0 = idx << 5;
        int rowEnd = row0 + 32; if (rowEnd > N) rowEnd = N;
        int lo = 0, hi = Bseg + 1;
        while (lo < hi) {
            int mid = (lo + hi) >> 1;
            long long v = is64 ? p64[mid] : (long long)p32[mid];
            if (v <= (long long)row0) lo = mid + 1; else hi = mid;
        }
        int s = lo - 1;
        long long nxt = is64 ? p64[s + 1] : (long long)p32[s + 1];
        for (int r = row0; r < rowEnd; ++r) {
            while (nxt <= (long long)r) {
                ++s;
                nxt = is64 ? p64[s + 1] : (long long)p32[s + 1];
            }
            g_seg_arr[r] = s;
        }
    }
}

// ---------------- fused MLP + segment-sum ----------------
__global__ __launch_bounds__(THREADS, 1)
void fused_mma(const float* __restrict__ x, const float* __restrict__ hn,
               const float* __restrict__ W1g, const float* __restrict__ b1g,
               const float* __restrict__ W2g, const float* __restrict__ b2g,
               float* __restrict__ out, int N) {
    extern __shared__ char smc[];
    uint2* W1F = (uint2*)(smc + W1F_OFF);
    uint2* W2F = (uint2*)(smc + W2F_OFF);
    float* b1s = (float*)(smc + B1_OFF);
    float* b2s = (float*)(smc + B2_OFF);

    const int tid  = threadIdx.x;
    const int lane = tid & 31;
    const int wid  = tid >> 5;

    // ---- build fp16 B-fragment images in smem (once per CTA) ----
    for (int s = tid; s < 9 * 16 * 32; s += THREADS) {
        int kb = s >> 9, nb = (s >> 5) & 15, ln = s & 31;
        int k0 = kb * 16 + 2 * (ln & 3);
        int n  = nb * 8 + (ln >> 2);
        uint32_t b0 = packh(W1g[k0 * 128 + n],       W1g[(k0 + 1) * 128 + n]);
        uint32_t b1 = packh(W1g[(k0 + 8) * 128 + n], W1g[(k0 + 9) * 128 + n]);
        W1F[s] = make_uint2(b0, b1);
    }
    for (int s = tid; s < 8 * 16 * 32; s += THREADS) {
        int kb = s >> 9, nb = (s >> 5) & 15, ln = s & 31;
        int k0 = kb * 16 + 2 * (ln & 3);
        int n  = nb * 8 + (ln >> 2);
        uint32_t b0 = packh(W2g[k0 * 128 + n],       W2g[(k0 + 1) * 128 + n]);
        uint32_t b1 = packh(W2g[(k0 + 8) * 128 + n], W2g[(k0 + 9) * 128 + n]);
        W2F[s] = make_uint2(b0, b1);
    }
    if (tid < 128) { b1s[tid] = b1g[tid]; b2s[tid] = b2g[tid]; }
    __syncthreads();

    uint32_t smem_u32;
    asm("{ .reg .u64 t; cvta.to.shared.u64 t, %1; cvt.u32.u64 %0, t; }"
        : "=r"(smem_u32) : "l"(smc));
    const uint32_t tile = smem_u32 + A_OFF + wid * WARP_TILE_B;

    const int rq = lane >> 2;
    const int c0 = 2 * (lane & 3);
    const int totalWarps = gridDim.x * NWARPS;
    const int wgid = blockIdx.x * NWARPS + wid;
    const int nIters = (N + 31) >> 5;
    const unsigned FM = 0xffffffffu;

    const int lm_row = lane & 15;
    const int lm_col = (lane >> 4) * 8;

    auto stage = [&](int it) {
        if (it >= nIters) return;
        const int base = it << 5;
        const float4 z4 = make_float4(0.f, 0.f, 0.f, 0.f);
        #pragma unroll
        for (int i = 0; i < 4; ++i) {
            int r = i * 8 + (lane >> 2);
            int g = base + r;
            float4 v = (g < N) ? *(const float4*)(x + (size_t)g * 16 + (lane & 3) * 4) : z4;
            sts64(tile + r * A_PITCH_B + (lane & 3) * 8,
                  packh(v.x, v.y), packh(v.z, v.w));
        }
        #pragma unroll 8
        for (int r = 0; r < 32; ++r) {
            int g = base + r;
            float4 v = (g < N) ? *(const float4*)(hn + (size_t)g * 128 + lane * 4) : z4;
            sts64(tile + r * A_PITCH_B + 32 + lane * 8,
                  packh(v.x, v.y), packh(v.z, v.w));
        }
    };

    stage(wgid);

    for (int it = wgid; it < nIters; it += totalWarps) {
        const int base = it << 5;
        __syncwarp();

        uint32_t hh[2][8][4];   // H fragments (fp16x2)

        // ---- GEMM1: K=144, two N-half passes ----
        #pragma unroll
        for (int hf = 0; hf < 2; ++hf) {
            float acc1[2][8][4];
            #pragma unroll
            for (int c = 0; c < 2; ++c)
                #pragma unroll
                for (int nb = 0; nb < 8; ++nb)
                    #pragma unroll
                    for (int j = 0; j < 4; ++j) acc1[c][nb][j] = 0.f;

            #pragma unroll
            for (int kb = 0; kb < 9; ++kb) {
                uint32_t a[2][4];
                #pragma unroll
                for (int c = 0; c < 2; ++c)
                    ldmx4(a[c], tile + (c * 16 + lm_row) * A_PITCH_B + (kb * 16 + lm_col) * 2);
                const uint2* w = W1F + kb * 512 + hf * 256 + lane;
                #pragma unroll
                for (int nbl = 0; nbl < 8; ++nbl) {
                    uint2 b = w[nbl * 32];
                    mma_f16(acc1[0][nbl], a[0], b.x, b.y);
                    mma_f16(acc1[1][nbl], a[1], b.x, b.y);
                }
            }

            // epilogue1 (this half): bias + relu + fp16 pack -> H fragments
            #pragma unroll
            for (int c = 0; c < 2; ++c) {
                #pragma unroll
                for (int k2 = 0; k2 < 4; ++k2) {
                    int nb0 = 2 * k2, nb1 = nb0 + 1;
                    int g0 = hf * 8 + nb0, g1 = hf * 8 + nb1;
                    float bb00 = b1s[g0 * 8 + c0], bb01 = b1s[g0 * 8 + c0 + 1];
                    float bb10 = b1s[g1 * 8 + c0], bb11 = b1s[g1 * 8 + c0 + 1];
                    uint32_t* hd = hh[c][hf * 4 + k2];
                    hd[0] = packh(fmaxf(acc1[c][nb0][0] + bb00, 0.f),
                                  fmaxf(acc1[c][nb0][1] + bb01, 0.f));
                    hd[1] = packh(fmaxf(acc1[c][nb0][2] + bb00, 0.f),
                                  fmaxf(acc1[c][nb0][3] + bb01, 0.f));
                    hd[2] = packh(fmaxf(acc1[c][nb1][0] + bb10, 0.f),
                                  fmaxf(acc1[c][nb1][1] + bb11, 0.f));
                    hd[3] = packh(fmaxf(acc1[c][nb1][2] + bb10, 0.f),
                                  fmaxf(acc1[c][nb1][3] + bb11, 0.f));
                }
            }
        }

        // A tile consumed; stage next iteration (LDG hides under GEMM2)
        __syncwarp();
        stage(it + totalWarps);

        // ---- seg ids + reduction masks ----
        int sg[2][2]; bool mk[2][2][3]; bool ld[2][2];
        #pragma unroll
        for (int c = 0; c < 2; ++c) {
            #pragma unroll
            for (int g = 0; g < 2; ++g) {
                int r = base + (2 * c + g) * 8 + rq;
                int s = (r < N) ? g_seg_arr[r] : -1;
                sg[c][g] = s;
                #pragma unroll
                for (int d = 0; d < 3; ++d) {
                    int t = __shfl_down_sync(FM, s, 4 << d);
                    mk[c][g][d] = (rq + (1 << d) < 8) && (t == s);
                }
                int pu = __shfl_up_sync(FM, s, 4);
                ld[c][g] = (rq == 0) || (pu != s);
            }
        }
        // uniform-32 fast-path test (warp-uniform)
        const int segFirst = __shfl_sync(FM, sg[0][0], 0);
        const int segLast  = __shfl_sync(FM, sg[1][1], 28);
        const bool uni32 = (base + 31 < N) && (segFirst == segLast);

        // ---- GEMM2 (K=128) in two N-half passes + fused epilogue2 ----
        #pragma unroll
        for (int nh = 0; nh < 2; ++nh) {
            float acc2[2][8][4];
            #pragma unroll
            for (int c = 0; c < 2; ++c)
                #pragma unroll
                for (int nb = 0; nb < 8; ++nb)
                    #pragma unroll
                    for (int j = 0; j < 4; ++j) acc2[c][nb][j] = 0.f;

            #pragma unroll
            for (int kb2 = 0; kb2 < 8; ++kb2) {
                const uint2* w = W2F + kb2 * 512 + nh * 256 + lane;
                #pragma unroll
                for (int nbl = 0; nbl < 8; ++nbl) {
                    uint2 b = w[nbl * 32];
                    mma_f16(acc2[0][nbl], hh[0][kb2], b.x, b.y);
                    mma_f16(acc2[1][nbl], hh[1][kb2], b.x, b.y);
                }
            }

            if (uni32) {
                // whole 32-row chunk is one segment: collapse groups first
                #pragma unroll
                for (int nbl = 0; nbl < 8; ++nbl) {
                    int nb = nh * 8 + nbl;
                    float bb0 = b2s[nb * 8 + c0], bb1 = b2s[nb * 8 + c0 + 1];
                    float V0 = acc2[0][nbl][0] + acc2[0][nbl][2]
                             + acc2[1][nbl][0] + acc2[1][nbl][2] + 4.f * bb0;
                    float V1 = acc2[0][nbl][1] + acc2[0][nbl][3]
                             + acc2[1][nbl][1] + acc2[1][nbl][3] + 4.f * bb1;
                    #pragma unroll
                    for (int d = 0; d < 3; ++d) {
                        int dd = 4 << d;
                        float t0 = __shfl_down_sync(FM, V0, dd);
                        float t1 = __shfl_down_sync(FM, V1, dd);
                        V0 += t0; V1 += t1;
                    }
                    if (lane < 4)
                        red_v2(out + (size_t)segFirst * 128 + nb * 8 + c0, V0, V1);
                }
            } else {
                #pragma unroll
                for (int c = 0; c < 2; ++c) {
                    #pragma unroll
                    for (int nbl = 0; nbl < 8; ++nbl) {
                        int nb = nh * 8 + nbl;
                        float bb0 = b2s[nb * 8 + c0], bb1 = b2s[nb * 8 + c0 + 1];
                        float v0 = acc2[c][nbl][0] + bb0;
                        float v1 = acc2[c][nbl][1] + bb1;
                        float v2 = acc2[c][nbl][2] + bb0;
                        float v3 = acc2[c][nbl][3] + bb1;
                        #pragma unroll
                        for (int d = 0; d < 3; ++d) {
                            int dd = 4 << d;
                            float t;
                            t = __shfl_down_sync(FM, v0, dd); if (mk[c][0][d]) v0 += t;
                            t = __shfl_down_sync(FM, v1, dd); if (mk[c][0][d]) v1 += t;
                            t = __shfl_down_sync(FM, v2, dd); if (mk[c][1][d]) v2 += t;
                            t = __shfl_down_sync(FM, v3, dd); if (mk[c][1][d]) v3 += t;
                        }
                        if (ld[c][0] && sg[c][0] >= 0)
                            red_v2(out + (size_t)sg[c][0] * 128 + nb * 8 + c0, v0, v1);
                        if (ld[c][1] && sg[c][1] >= 0)
                            red_v2(out + (size_t)sg[c][1] * 128 + nb * 8 + c0, v2, v3);
                    }
                }
            }
        }
    }
}

// ---------------- launch ----------------
extern "C" void kernel_launch(void* const* d_in, const int* in_sizes, int n_in,
                              void* d_out, int out_size) {
    const float* x  = (const float*)d_in[0];
    const float* hn = (const float*)d_in[1];
    const void*  pt = d_in[2];
    const float* W1 = (const float*)d_in[3];
    const float* b1 = (const float*)d_in[4];
    const float* W2 = (const float*)d_in[5];
    const float* b2 = (const float*)d_in[6];
    float* out = (float*)d_out;

    int N    = in_sizes[0] / 16;
    int Bseg = in_sizes[2] - 1;

    int out4 = out_size / 4;
    int nWalk = (N + 31) >> 5;
    int prep_n = (out4 > nWalk) ? out4 : nWalk;
    prep_kernel<<<(prep_n + 255) / 256, 256>>>(pt, (float4*)out, out4, Bseg, N);

    cudaFuncSetAttribute(fused_mma, cudaFuncAttributeMaxDynamicSharedMemorySize, SMEM_BYTES);
    int sms = 0;
    cudaDeviceGetAttribute(&sms, cudaDevAttrMultiProcessorCount, 0);
    if (sms <= 0) sms = 148;
    int nIters = (N + 31) >> 5;
    int maxCtas = (nIters + NWARPS - 1) / NWARPS;
    int grid = (sms < maxCtas) ? sms : maxCtas;
    fused_mma<<<grid, THREADS, SMEM_BYTES>>>(x, hn, W1, b1, W2, b2, out, N);
}